// round 16
// baseline (speedup 1.0000x reference)
#include <cuda_runtime.h>
#include <math.h>

#define VOL (256*128*128)     /* 4194304 full padded volume */
#define NB  (128*64*64)       /* 524288  crop / attention block */
#define RG  256               /* blocks per f per reduction stage */
#define SMP 129               /* smem tile pitch (float2) */

// ---------------- scratch (static device allocations, no runtime alloc) ----------------
static __device__ float2 g_bufA[2*(size_t)VOL];   // Z spectra per bd (t<128 used)
static __device__ float2 g_bufB[4*(size_t)VOL];   // P,R per bd (t<128 used)
static __device__ float2 g_zc[2*(size_t)NB];      // conv+mtx packed complex (cos + i sin)
static __device__ float  g_sq[2*(size_t)NB];      // sqrt(mag) crop
static __device__ float2 g_Wf[(size_t)VOL];       // filtered W(k)/256
static __device__ float  g_Mc[128*128];
static __device__ float  g_Ms[128*128];
static __device__ float2 g_tw[128];               // W_256^k, k<128 (forward sign)
static __device__ float  g_sinT[128];             // sin(t), t=0..127

// attention reduction state
static __device__ double g_pD[2][RG];
static __device__ float  g_pMnL[2][RG], g_pMxL[2][RG], g_pMnH[2][RG], g_pMxH[2][RG];
static __device__ unsigned g_ctr[4][2];           // zero-init; self-resetting via atomicInc wrap
static __device__ float  g_a1[2], g_c1[2], g_M1f[2], g_Z1i[2];
static __device__ float  g_a2[2], g_c2[2], g_M2f[2], g_Z2i[2];
static __device__ float  g_mnH[2], g_mxH[2];

__device__ __forceinline__ float2 cmul(float2 a, float2 b){
    return make_float2(a.x*b.x - a.y*b.y, a.x*b.y + a.y*b.x);
}
__device__ __forceinline__ float2 cadd(float2 a, float2 b){ return make_float2(a.x+b.x, a.y+b.y); }
__device__ __forceinline__ float2 csub(float2 a, float2 b){ return make_float2(a.x-b.x, a.y-b.y); }

// ---------------- register FFT machinery ----------------
template<int SGN>
__device__ __forceinline__ float2 twd(const float2* stw, int m){
    m &= 255;
    float2 w = (m < 128) ? stw[m] : make_float2(-stw[m-128].x, -stw[m-128].y);
    if (SGN < 0) w.y = -w.y;
    return w;
}

template<int SGN>
__device__ __forceinline__ void bfly4(float2&a,float2&b,float2&c,float2&d){
    float2 t0=cadd(a,c), t1=csub(a,c), t2=cadd(b,d), t3=csub(b,d);
    float2 it3 = (SGN>0)? make_float2(t3.y,-t3.x) : make_float2(-t3.y,t3.x);
    a=cadd(t0,t2); c=csub(t0,t2);
    b=cadd(t1,it3); d=csub(t1,it3);
}

template<int SGN>
__device__ __forceinline__ void fft16(float2 r[16], const float2* stw){
    #pragma unroll
    for(int a=0;a<4;a++){
        bfly4<SGN>(r[a], r[a+4], r[a+8], r[a+12]);
        #pragma unroll
        for(int k1=1;k1<4;k1++)
            r[a+4*k1] = cmul(r[a+4*k1], twd<SGN>(stw, 16*a*k1));
    }
    #pragma unroll
    for(int k1=0;k1<4;k1++)
        bfly4<SGN>(r[4*k1], r[4*k1+1], r[4*k1+2], r[4*k1+3]);
    float2 tmp[16];
    #pragma unroll
    for(int i=0;i<16;i++) tmp[((i&3)<<2)|(i>>2)] = r[i];
    #pragma unroll
    for(int i=0;i<16;i++) r[i]=tmp[i];
}

template<int SGN>
__device__ __forceinline__ void fft8(float2 r[8], const float2* stw){
    #pragma unroll
    for(int a=0;a<4;a++){
        float2 u=r[a], v=r[a+4];
        r[a]=cadd(u,v); r[a+4]=csub(u,v);
    }
    #pragma unroll
    for(int a=1;a<4;a++)
        r[a+4]=cmul(r[a+4], twd<SGN>(stw, 32*a));   // W8^a
    bfly4<SGN>(r[0],r[1],r[2],r[3]);
    bfly4<SGN>(r[4],r[5],r[6],r[7]);
    float2 tmp[8];
    #pragma unroll
    for(int m=0;m<8;m++){ int p=m>>2, q=m&3; tmp[2*q+p]=r[m]; }
    #pragma unroll
    for(int m=0;m<8;m++) r[m]=tmp[m];
}

// ---------------- init ----------------
__global__ void k_init_tw(){
    int i = threadIdx.x;
    if (i < 128){
        double a = -2.0*3.14159265358979323846*(double)i/256.0;
        double s, c; sincos(a, &s, &c);
        g_tw[i] = make_float2((float)c, (float)s);
        g_sinT[i] = (float)sin((double)i);
    }
}

// Mc[t][j] = sum_m mtx[t][m] * waveC[j-m+31] (k=63 taps), same for Ms
__global__ void k_build_M(const float* __restrict__ mtx, const float* __restrict__ wave){
    int idx = blockIdx.x*blockDim.x + threadIdx.x;
    if (idx >= 128*128) return;
    int t = idx >> 7, j = idx & 127;
    float ac = 0.f, as = 0.f;
    for (int m = 0; m < 128; m++){
        int tau = j - m + 31;
        if (tau >= 0 && tau < 63){
            float mv = mtx[t*128 + m];
            ac = fmaf(mv, wave[tau],      ac);
            as = fmaf(mv, wave[63 + tau], as);
        }
    }
    g_Mc[idx] = ac; g_Ms[idx] = as;
}

// ---------------- conv+mtx -> packed complex (w-split: 256 blocks) ----------------
__global__ __launch_bounds__(512) void k_conv(const float* __restrict__ feat){
    __shared__ float sx[128*32];
    int bid = blockIdx.x;
    int bd = bid >> 7, r = bid & 127, h = r >> 1, wo = (r & 1)*32;
    const float* src = feat + (size_t)bd*NB + h*64 + wo;
    for (int i = threadIdx.x; i < 128*32; i += 512){
        int t = i >> 5, wl = i & 31;
        sx[i] = src[(size_t)t*4096 + wl];
    }
    __syncthreads();
    float2* dst = g_zc + (size_t)bd*NB + h*64 + wo;
    for (int o = threadIdx.x; o < 128*32; o += 512){
        int t = o >> 5, wl = o & 31;
        float ac = 0.f, as = 0.f;
        const float* mc = g_Mc + t*128;
        const float* ms = g_Ms + t*128;
        #pragma unroll 8
        for (int m = 0; m < 128; m++){
            float xv = sx[m*32 + wl];
            ac = fmaf(mc[m], xv, ac);
            as = fmaf(ms[m], xv, as);
        }
        dst[(size_t)t*4096 + wl] = make_float2(ac, as);
    }
}

// ---------------- forward 2D (H,W) FFT per t-slice (register four-step) ----------------
__global__ __launch_bounds__(512,1) void k_fwd2D(){
    extern __shared__ float2 sm[];           // 128*SMP
    __shared__ float2 stw[128];
    int tid = threadIdx.x;
    if (tid < 128) stw[tid] = g_tw[tid];
    int t = blockIdx.x, bd = blockIdx.y;
    float2* S = sm + 64*SMP;                 // 64 x SMP region
    const float2* src = g_zc + (size_t)bd*NB + (size_t)t*4096;

    for (int i = tid; i < 64*64; i += 512){
        int h = i >> 6, w = i & 63;
        S[h*SMP + w] = src[i];
    }
    __syncthreads();

    // phase W
    {
        int h = tid & 63, r = tid >> 6;
        float2 X[16];
        #pragma unroll
        for (int n2 = 0; n2 < 8; n2++) X[n2] = S[h*SMP + r + 8*n2];
        #pragma unroll
        for (int n2 = 8; n2 < 16; n2++) X[n2] = make_float2(0.f,0.f);
        fft16<1>(X, stw);
        #pragma unroll
        for (int k2 = 1; k2 < 16; k2++) X[k2] = cmul(X[k2], twd<1>(stw, 2*r*k2));
        #pragma unroll
        for (int k2 = 0; k2 < 16; k2++) sm[h*SMP + k2*8 + r] = X[k2];
    }
    __syncthreads();
    {
        int h = tid & 63, rp = tid >> 6;
        #pragma unroll
        for (int kk = 0; kk < 2; kk++){
            int k2 = 2*rp + kk;
            float2 r8[8];
            #pragma unroll
            for (int n1 = 0; n1 < 8; n1++) r8[n1] = sm[h*SMP + k2*8 + n1];
            fft8<1>(r8, stw);
            #pragma unroll
            for (int k1 = 0; k1 < 8; k1++) S[h*SMP + k2 + 16*k1] = r8[k1];
        }
    }

    // phase H: 128 columns in two groups of 64
    for (int g = 0; g < 2; g++){
        __syncthreads();
        int cl = tid & 63, r = tid >> 6;
        float2 X[16];
        #pragma unroll
        for (int n2 = 0; n2 < 8; n2++) X[n2] = S[(r + 8*n2)*SMP + g*64 + cl];
        #pragma unroll
        for (int n2 = 8; n2 < 16; n2++) X[n2] = make_float2(0.f,0.f);
        fft16<1>(X, stw);
        #pragma unroll
        for (int k2 = 1; k2 < 16; k2++) X[k2] = cmul(X[k2], twd<1>(stw, 2*r*k2));
        #pragma unroll
        for (int k2 = 0; k2 < 16; k2++) sm[cl*SMP + k2*8 + r] = X[k2];
        __syncthreads();
        float2* dst = g_bufA + (size_t)bd*VOL + (size_t)t*16384 + g*64 + cl;
        #pragma unroll
        for (int kk = 0; kk < 2; kk++){
            int k2 = 2*r + kk;
            float2 r8[8];
            #pragma unroll
            for (int n1 = 0; n1 < 8; n1++) r8[n1] = sm[cl*SMP + k2*8 + n1];
            fft8<1>(r8, stw);
            #pragma unroll
            for (int k1 = 0; k1 < 8; k1++) dst[(size_t)(k2 + 16*k1)*128] = r8[k1];
        }
    }
}

// ---------------- fused reduction stages (partials + last-block combine) ----------------
__device__ __forceinline__ float elemL(const float* K, int j, float& kL){
    int tl = j >> 12, hl = (j >> 6) & 63, wl = j & 63;
    float vL = K[((192 + tl) & 255)*16384 + ((96 + hl) & 127)*128 + ((96 + wl) & 127)];
    kL = vL + g_sinT[tl];
    return vL;
}
__device__ __forceinline__ void elemH(const float* K, int j, float& kH){
    int tl = j >> 12, hl = (j >> 6) & 63, wl = j & 63;
    float vH = K[(64 + tl)*16384 + (32 + hl)*128 + (32 + wl)];
    kH = vH + g_sinT[tl];
}

__device__ double blockRedD(double v){
    __shared__ double sh[8];
    int lane = threadIdx.x & 31, wid = threadIdx.x >> 5;
    #pragma unroll
    for (int o = 16; o; o >>= 1) v += __shfl_down_sync(0xffffffffu, v, o);
    if (lane == 0) sh[wid] = v;
    __syncthreads();
    if (wid == 0){
        v = (lane < 8) ? sh[lane] : 0.0;
        #pragma unroll
        for (int o = 4; o; o >>= 1) v += __shfl_down_sync(0xffffffffu, v, o);
    }
    __syncthreads();
    return v;   // valid in tid 0
}

__device__ void blockRed5(double& s, float& mnL, float& mxL, float& mnH, float& mxH){
    __shared__ double shD[8];
    __shared__ float sh1[8], sh2[8], sh3[8], sh4[8];
    int lane = threadIdx.x & 31, wid = threadIdx.x >> 5;
    #pragma unroll
    for (int o = 16; o; o >>= 1){
        s   += __shfl_down_sync(0xffffffffu, s, o);
        mnL  = fminf(mnL, __shfl_down_sync(0xffffffffu, mnL, o));
        mxL  = fmaxf(mxL, __shfl_down_sync(0xffffffffu, mxL, o));
        mnH  = fminf(mnH, __shfl_down_sync(0xffffffffu, mnH, o));
        mxH  = fmaxf(mxH, __shfl_down_sync(0xffffffffu, mxH, o));
    }
    if (lane == 0){ shD[wid]=s; sh1[wid]=mnL; sh2[wid]=mxL; sh3[wid]=mnH; sh4[wid]=mxH; }
    __syncthreads();
    if (wid == 0){
        s   = (lane < 8) ? shD[lane] : 0.0;
        mnL = (lane < 8) ? sh1[lane] :  3.4e38f;
        mxL = (lane < 8) ? sh2[lane] : -3.4e38f;
        mnH = (lane < 8) ? sh3[lane] :  3.4e38f;
        mxH = (lane < 8) ? sh4[lane] : -3.4e38f;
        #pragma unroll
        for (int o = 4; o; o >>= 1){
            s   += __shfl_down_sync(0xffffffffu, s, o);
            mnL  = fminf(mnL, __shfl_down_sync(0xffffffffu, mnL, o));
            mxL  = fmaxf(mxL, __shfl_down_sync(0xffffffffu, mxL, o));
            mnH  = fminf(mnH, __shfl_down_sync(0xffffffffu, mnH, o));
            mxH  = fmaxf(mxH, __shfl_down_sync(0xffffffffu, mxH, o));
        }
    }
    __syncthreads();
}

__global__ __launch_bounds__(256) void k_stageA(const float* __restrict__ invr, const float* __restrict__ invi,
                                                const float* __restrict__ wp, const float* __restrict__ bp){
    int f = blockIdx.y; const float* K = f ? invi : invr;
    int tid = threadIdx.x;
    double sum = 0.0;
    float mnL = 3.4e38f, mxL = -3.4e38f, mnH = 3.4e38f, mxH = -3.4e38f;
    for (int j = blockIdx.x*256 + tid; j < NB; j += RG*256){
        float kL, kH;
        float vL = elemL(K, j, kL);
        elemH(K, j, kH);
        sum += (double)vL;
        mnL = fminf(mnL, kL); mxL = fmaxf(mxL, kL);
        mnH = fminf(mnH, kH); mxH = fmaxf(mxH, kH);
    }
    blockRed5(sum, mnL, mxL, mnH, mxH);
    __shared__ int sLast;
    if (tid == 0){
        g_pD[f][blockIdx.x] = sum;
        g_pMnL[f][blockIdx.x] = mnL; g_pMxL[f][blockIdx.x] = mxL;
        g_pMnH[f][blockIdx.x] = mnH; g_pMxH[f][blockIdx.x] = mxH;
        __threadfence();
        unsigned r = atomicInc(&g_ctr[0][f], RG - 1);
        sLast = (r == RG - 1);
    }
    __syncthreads();
    if (sLast){
        double s2 = g_pD[f][tid];
        float m1 = g_pMnL[f][tid], m2 = g_pMxL[f][tid];
        float m3 = g_pMnH[f][tid], m4 = g_pMxH[f][tid];
        blockRed5(s2, m1, m2, m3, m4);
        if (tid == 0){
            float W = *wp, B = *bp;
            float scal1 = W*(float)(s2/(double)NB) + B;
            float a1 = scal1*W, c1 = scal1*B;
            g_a1[f] = a1; g_c1[f] = c1;
            g_M1f[f] = (a1 >= 0.f ? a1*m2 : a1*m1) + c1;
            g_mnH[f] = m3; g_mxH[f] = m4;
        }
    }
}

__global__ __launch_bounds__(256) void k_stageB(const float* __restrict__ invr, const float* __restrict__ invi){
    int f = blockIdx.y; const float* K = f ? invi : invr;
    int tid = threadIdx.x;
    float a1 = g_a1[f], c1 = g_c1[f], M1 = g_M1f[f];
    double acc = 0.0;
    for (int j = blockIdx.x*256 + tid; j < NB; j += RG*256){
        float kL; elemL(K, j, kL);
        acc += (double)__expf(fmaf(a1, kL, c1) - M1);
    }
    acc = blockRedD(acc);
    __shared__ int sLast;
    if (tid == 0){
        g_pD[f][blockIdx.x] = acc;
        __threadfence();
        unsigned r = atomicInc(&g_ctr[1][f], RG - 1);
        sLast = (r == RG - 1);
    }
    __syncthreads();
    if (sLast){
        double s2 = blockRedD(g_pD[f][tid]);
        if (tid == 0) g_Z1i[f] = (float)(1.0/s2);
    }
}

__global__ __launch_bounds__(256) void k_stageC(const float* __restrict__ invr, const float* __restrict__ invi,
                                                const float* __restrict__ wp, const float* __restrict__ bp){
    int f = blockIdx.y; const float* K = f ? invi : invr;
    int tid = threadIdx.x;
    float a1 = g_a1[f], c1 = g_c1[f], M1 = g_M1f[f], Z1i = g_Z1i[f];
    double acc = 0.0;
    for (int j = blockIdx.x*256 + tid; j < NB; j += RG*256){
        float kL; elemL(K, j, kL);
        float sm = __expf(fmaf(a1, kL, c1) - M1) * Z1i;
        acc += (double)(kL / (1.f + __expf(-sm)));
    }
    acc = blockRedD(acc);
    __shared__ int sLast;
    if (tid == 0){
        g_pD[f][blockIdx.x] = acc;
        __threadfence();
        unsigned r = atomicInc(&g_ctr[2][f], RG - 1);
        sLast = (r == RG - 1);
    }
    __syncthreads();
    if (sLast){
        double s2 = blockRedD(g_pD[f][tid]);
        if (tid == 0){
            float W = *wp, B = *bp;
            float scal2 = W*(float)(s2/(double)NB) + B;
            float a2 = scal2*W, c2 = scal2*B;
            g_a2[f] = a2; g_c2[f] = c2;
            g_M2f[f] = (a2 >= 0.f ? a2*g_mxH[f] : a2*g_mnH[f]) + c2;
        }
    }
}

__global__ __launch_bounds__(256) void k_stageD(const float* __restrict__ invr, const float* __restrict__ invi){
    int f = blockIdx.y; const float* K = f ? invi : invr;
    int tid = threadIdx.x;
    float a2 = g_a2[f], c2 = g_c2[f], M2 = g_M2f[f];
    double acc = 0.0;
    for (int j = blockIdx.x*256 + tid; j < NB; j += RG*256){
        float kH; elemH(K, j, kH);
        acc += (double)__expf(fmaf(a2, kH, c2) - M2);
    }
    acc = blockRedD(acc);
    __shared__ int sLast;
    if (tid == 0){
        g_pD[f][blockIdx.x] = acc;
        __threadfence();
        unsigned r = atomicInc(&g_ctr[3][f], RG - 1);
        sLast = (r == RG - 1);
    }
    __syncthreads();
    if (sLast){
        double s2 = blockRedD(g_pD[f][tid]);
        if (tid == 0) g_Z2i[f] = (float)(1.0/s2);
    }
}

// ---------------- attention filter (pointwise) ----------------
__device__ __forceinline__ float atten_filter(float v, int t, int h, int w, int f){
    int tl = t - 64, hl = h - 32, wl = w - 32;
    if ((unsigned)tl < 128u && (unsigned)hl < 64u && (unsigned)wl < 64u){
        float k2p = v + g_sinT[tl];
        float sm = __expf(fmaf(g_a2[f], k2p, g_c2[f]) - g_M2f[f]) * g_Z2i[f];
        return k2p / (1.f + __expf(-sm));
    }
    int tl2 = (t + 64) & 255, hl2 = (h + 32) & 127, wl2 = (w + 32) & 127;
    if (tl2 < 128 && hl2 < 64 && wl2 < 64){
        float k2p = v + g_sinT[tl2];
        float sm = __expf(fmaf(g_a1[f], k2p, g_c1[f]) - g_M1f[f]) * g_Z1i[f];
        return k2p / (1.f + __expf(-sm));
    }
    return v;
}

// ---------------- precompute filtered W volume: W(k)/256 (float2) ----------------
__global__ __launch_bounds__(256) void k_filterW(const float* __restrict__ invr, const float* __restrict__ invi){
    int idx = blockIdx.x*256 + threadIdx.x;
    int t = idx >> 14, h = (idx >> 7) & 127, w = idx & 127;
    const float sc = 1.f/256.f;
    float w1 = atten_filter(invr[idx], t, h, w, 0)*sc;
    float w2 = atten_filter(invi[idx], t, h, w, 1)*sc;
    g_Wf[idx] = make_float2(w1, w2);
}

// ---------------- fused T (16x16 four-step, register FFTs) ----------------
__global__ __launch_bounds__(256,2) void k_fusedT(){
    extern __shared__ unsigned char smraw[];
    float2* bufA = (float2*)smraw;           // 16 lanes x 257
    float2* bufB = bufA + 16*257;
    __shared__ float2 stw[128];
    int tid = threadIdx.x, lane = tid & 15, role = tid >> 4;
    if (tid < 128) stw[tid] = g_tw[tid];
    int wb = blockIdx.x << 4, h = blockIdx.y, bd = blockIdx.z;
    int w = wb + lane;

    float2 X[16];
    const float2* ZS = g_bufA + (size_t)bd*VOL + (size_t)h*128 + w;
    #pragma unroll
    for (int j = 0; j < 8; j++) X[j] = ZS[(size_t)(role + 16*j)*16384];
    #pragma unroll
    for (int j = 8; j < 16; j++) X[j] = make_float2(0.f, 0.f);
    __syncthreads();

    fft16<1>(X, stw);
    int base = lane*257;
    #pragma unroll
    for (int j = 1; j < 16; j++) X[j] = cmul(X[j], twd<1>(stw, role*j));
    #pragma unroll
    for (int j = 0; j < 16; j++) bufA[base + j*16 + role] = X[j];
    __syncthreads();
    float2 S[16];
    #pragma unroll
    for (int n1 = 0; n1 < 16; n1++) S[n1] = bufA[base + role*16 + n1];
    fft16<1>(S, stw);

    const float2* WD = g_Wf + (size_t)h*128 + w;
    float2 A[16];
    #pragma unroll
    for (int j = 0; j < 16; j++){
        float2 wd = WD[(size_t)(role + 16*j)*16384];
        A[j] = cmul(wd, S[j]);
    }
    fft16<-1>(A, stw);
    __syncthreads();
    #pragma unroll
    for (int t1 = 0; t1 < 16; t1++)
        bufA[base + t1*16 + role] = cmul(A[t1], twd<-1>(stw, role*t1));

    int hn = (128 - h) & 127, wn = (128 - w) & 127;
    const float2* WR = g_Wf + (size_t)hn*128 + wn;
    #pragma unroll
    for (int j = 0; j < 16; j++){
        int kn = (256 - (role + 16*j)) & 255;
        float2 wr = WR[(size_t)kn*16384];
        A[j] = cmul(make_float2(wr.x, -wr.y), S[j]);
    }
    fft16<-1>(A, stw);
    #pragma unroll
    for (int t1 = 0; t1 < 16; t1++)
        bufB[base + t1*16 + role] = cmul(A[t1], twd<-1>(stw, role*t1));
    __syncthreads();

    float2* dP = g_bufB + (size_t)(2*bd)*VOL + (size_t)h*128 + w;
    #pragma unroll
    for (int K = 0; K < 16; K++) A[K] = bufA[base + role*16 + K];
    fft16<-1>(A, stw);
    #pragma unroll
    for (int t2 = 0; t2 < 8; t2++) dP[(size_t)(role + 16*t2)*16384] = A[t2];
    #pragma unroll
    for (int K = 0; K < 16; K++) A[K] = bufB[base + role*16 + K];
    fft16<-1>(A, stw);
    #pragma unroll
    for (int t2 = 0; t2 < 8; t2++) dP[(size_t)VOL + (size_t)(role + 16*t2)*16384] = A[t2];
}

// ---------------- inverse 2D (H,W) per t-slice (register four-step) -----------------
__global__ __launch_bounds__(512,1) void k_inv2D(){
    extern __shared__ float2 sm[];           // 128*SMP: rows 0..63 = exchange E, 64..127 = O
    __shared__ float2 stw[128];
    __shared__ float2 qd[64*65];
    int tid = threadIdx.x;
    if (tid < 128){ stw[tid] = g_tw[tid]; }
    int t = blockIdx.x, bd = blockIdx.y;
    float2* O = sm + 64*SMP;

    for (int pass = 0; pass < 2; pass++){
        const float2* src = g_bufB + (size_t)(2*bd + pass)*VOL + (size_t)t*16384;
        for (int g = 0; g < 2; g++){
            __syncthreads();
            int cl = tid & 63, r = tid >> 6;
            float2 X[16];
            #pragma unroll
            for (int n2 = 0; n2 < 16; n2++) X[n2] = src[(size_t)(r + 8*n2)*128 + g*64 + cl];
            fft16<-1>(X, stw);
            #pragma unroll
            for (int k2 = 1; k2 < 16; k2++) X[k2] = cmul(X[k2], twd<-1>(stw, 2*r*k2));
            #pragma unroll
            for (int k2 = 0; k2 < 16; k2++) sm[cl*SMP + k2*8 + r] = X[k2];
            __syncthreads();
            #pragma unroll
            for (int kk = 0; kk < 2; kk++){
                int k2 = 2*r + kk;
                float2 r8[8];
                #pragma unroll
                for (int n1 = 0; n1 < 8; n1++) r8[n1] = sm[cl*SMP + k2*8 + n1];
                fft8<-1>(r8, stw);
                #pragma unroll
                for (int k1 = 0; k1 < 4; k1++) O[(k2 + 16*k1)*SMP + g*64 + cl] = r8[k1];
            }
        }
        __syncthreads();
        {
            int h = tid & 63, r = tid >> 6;
            float2 X[16];
            #pragma unroll
            for (int n2 = 0; n2 < 16; n2++) X[n2] = O[h*SMP + r + 8*n2];
            fft16<-1>(X, stw);
            #pragma unroll
            for (int k2 = 1; k2 < 16; k2++) X[k2] = cmul(X[k2], twd<-1>(stw, 2*r*k2));
            #pragma unroll
            for (int k2 = 0; k2 < 16; k2++) sm[h*SMP + k2*8 + r] = X[k2];
        }
        __syncthreads();
        {
            int h = tid & 63, r = tid >> 6;
            float* fq = (float*)O;
            #pragma unroll
            for (int kk = 0; kk < 2; kk++){
                int k2 = 2*r + kk;
                float2 r8[8];
                #pragma unroll
                for (int n1 = 0; n1 < 8; n1++) r8[n1] = sm[h*SMP + k2*8 + n1];
                fft8<-1>(r8, stw);
                if (pass == 0){
                    #pragma unroll
                    for (int k1 = 0; k1 < 4; k1++)
                        qd[h*65 + k2 + 16*k1] = r8[k1];
                } else {
                    const float S2 = 1.f/268435456.f;   // (1/16384)^2
                    #pragma unroll
                    for (int k1 = 0; k1 < 4; k1++){
                        int w = k2 + 16*k1;
                        float2 P = qd[h*65 + w];
                        float2 R = r8[k1];
                        float Sr = (P.x*R.x + P.y*R.y)*S2;
                        float Si = (P.y*R.x - P.x*R.y)*S2;
                        float mag = fmaxf(0.5f*(sqrtf(Sr*Sr + Si*Si) + Sr), 0.f);
                        fq[h*65 + w] = sqrtf(mag);
                    }
                }
            }
        }
        if (pass == 1){
            __syncthreads();
            const float* fq = (const float*)O;
            float* dst = g_sq + (size_t)bd*NB + (size_t)t*4096;
            for (int i = tid; i < 4096; i += 512)
                dst[i] = fq[(i >> 6)*65 + (i & 63)];
        }
    }
}

// ---------------- final mtxi matmul along T (w-split: 256 blocks) ----------------
__global__ __launch_bounds__(512) void k_final(const float* __restrict__ mtxi, float* __restrict__ out){
    __shared__ float sx[128*32];
    int bid = blockIdx.x;
    int bd = bid >> 7, r = bid & 127, h = r >> 1, wo = (r & 1)*32;
    const float* src = g_sq + (size_t)bd*NB + h*64 + wo;
    for (int i = threadIdx.x; i < 128*32; i += 512){
        int t = i >> 5, wl = i & 31;
        sx[i] = src[(size_t)t*4096 + wl];
    }
    __syncthreads();
    float* dst = out + (size_t)bd*NB + h*64 + wo;
    for (int o = threadIdx.x; o < 128*32; o += 512){
        int t = o >> 5, wl = o & 31;
        float acc = 0.f;
        const float* mi = mtxi + t*128;
        #pragma unroll 8
        for (int m = 0; m < 128; m++) acc = fmaf(mi[m], sx[m*32 + wl], acc);
        dst[(size_t)t*4096 + wl] = acc;
    }
}

// ---------------- launch ----------------
#define TILE_SMEM (128*SMP*8)
#define FT_SMEM   (2*16*257*8)

extern "C" void kernel_launch(void* const* d_in, const int* in_sizes, int n_in,
                              void* d_out, int out_size){
    const float *feature = 0, *conv_w = 0, *conv_b = 0, *wave = 0;
    const float *invr = 0, *invi = 0, *mtx = 0, *mtxi = 0;
    int scal_seen = 0, mat_seen = 0, psf_seen = 0;
    for (int i = 0; i < n_in; i++){
        const float* p = (const float*)d_in[i];
        int s = in_sizes[i];
        if      (s == 1)       { if (scal_seen++ == 0) conv_w = p; else conv_b = p; }
        else if (s == 126)     wave = p;
        else if (s == 16384)   { if (mat_seen++ == 0) mtx = p; else mtxi = p; }
        else if (s == 4194304) { if (psf_seen++ == 0) invr = p; else invi = p; }
        else if (s == 1048576) feature = p;
    }
    float* out = (float*)d_out;

    // lazy one-time resources (no device memory; same launches every call)
    static cudaStream_t s2 = 0;
    static cudaEvent_t  evFork = 0, evJoin = 0;
    static int attrs_set = 0;
    if (!s2){
        cudaStreamCreateWithFlags(&s2, cudaStreamNonBlocking);
        cudaEventCreateWithFlags(&evFork, cudaEventDisableTiming);
        cudaEventCreateWithFlags(&evJoin, cudaEventDisableTiming);
    }
    if (!attrs_set){
        cudaFuncSetAttribute(k_fwd2D,  cudaFuncAttributeMaxDynamicSharedMemorySize, TILE_SMEM);
        cudaFuncSetAttribute(k_inv2D,  cudaFuncAttributeMaxDynamicSharedMemorySize, TILE_SMEM);
        cudaFuncSetAttribute(k_fusedT, cudaFuncAttributeMaxDynamicSharedMemorySize, FT_SMEM);
        attrs_set = 1;
    }

    k_init_tw<<<1,128>>>();

    // fork: side stream runs the attention-scalar chain + filterW (needs only g_sinT)
    cudaEventRecord(evFork, 0);
    cudaStreamWaitEvent(s2, evFork, 0);

    k_stageA<<<dim3(RG,2),256,0,s2>>>(invr, invi, conv_w, conv_b);
    k_stageB<<<dim3(RG,2),256,0,s2>>>(invr, invi);
    k_stageC<<<dim3(RG,2),256,0,s2>>>(invr, invi, conv_w, conv_b);
    k_stageD<<<dim3(RG,2),256,0,s2>>>(invr, invi);
    k_filterW<<<VOL/256,256,0,s2>>>(invr, invi);
    cudaEventRecord(evJoin, s2);

    // main stream: forward path
    k_build_M<<<64,256>>>(mtx, wave);
    k_conv<<<256,512>>>(feature);
    k_fwd2D<<<dim3(128,2),512,TILE_SMEM>>>();

    // join before fusedT (needs g_bufA AND g_Wf)
    cudaStreamWaitEvent(0, evJoin, 0);

    k_fusedT<<<dim3(8,128,2),256,FT_SMEM>>>();
    k_inv2D<<<dim3(128,2),512,TILE_SMEM>>>();
    k_final<<<256,512>>>(mtxi, out);
}

// round 17
// speedup vs baseline: 1.1081x; 1.1081x over previous
#include <cuda_runtime.h>
#include <math.h>

#define VOL (256*128*128)     /* 4194304 full padded volume */
#define NB  (128*64*64)       /* 524288  crop / attention block */
#define RBLK 512
#define SMP 129               /* smem tile pitch (float2) */

// ---------------- scratch (static device allocations, no runtime alloc) ----------------
static __device__ float2 g_bufA[2*(size_t)VOL];   // Z spectra per bd (t<128 used)
static __device__ float2 g_bufB[4*(size_t)VOL];   // P,R per bd (t<128 used)
static __device__ float2 g_zc[2*(size_t)NB];      // conv+mtx packed complex (cos + i sin)
static __device__ float  g_sq[2*(size_t)NB];      // sqrt(mag) crop
static __device__ float2 g_Wf[(size_t)VOL];       // filtered W(k)/256
static __device__ float  g_Mc[128*128];
static __device__ float  g_Ms[128*128];
static __device__ float2 g_tw[128];               // W_256^k, k<128 (forward sign)
static __device__ float  g_sinT[128];             // sin(t), t=0..127

// attention reduction state
static __device__ double g_pD[2][RBLK];
static __device__ float  g_pMnL[2][RBLK], g_pMxL[2][RBLK], g_pMnH[2][RBLK], g_pMxH[2][RBLK];
static __device__ float  g_a1[2], g_c1[2], g_M1f[2], g_Z1i[2];
static __device__ float  g_a2[2], g_c2[2], g_M2f[2], g_Z2i[2];
static __device__ float  g_mnH[2], g_mxH[2];

__device__ __forceinline__ float2 cmul(float2 a, float2 b){
    return make_float2(a.x*b.x - a.y*b.y, a.x*b.y + a.y*b.x);
}
__device__ __forceinline__ float2 cadd(float2 a, float2 b){ return make_float2(a.x+b.x, a.y+b.y); }
__device__ __forceinline__ float2 csub(float2 a, float2 b){ return make_float2(a.x-b.x, a.y-b.y); }

// ---------------- register FFT machinery ----------------
template<int SGN>
__device__ __forceinline__ float2 twd(const float2* stw, int m){
    m &= 255;
    float2 w = (m < 128) ? stw[m] : make_float2(-stw[m-128].x, -stw[m-128].y);
    if (SGN < 0) w.y = -w.y;
    return w;
}

template<int SGN>
__device__ __forceinline__ void bfly4(float2&a,float2&b,float2&c,float2&d){
    float2 t0=cadd(a,c), t1=csub(a,c), t2=cadd(b,d), t3=csub(b,d);
    float2 it3 = (SGN>0)? make_float2(t3.y,-t3.x) : make_float2(-t3.y,t3.x);
    a=cadd(t0,t2); c=csub(t0,t2);
    b=cadd(t1,it3); d=csub(t1,it3);
}

template<int SGN>
__device__ __forceinline__ void fft16(float2 r[16], const float2* stw){
    #pragma unroll
    for(int a=0;a<4;a++){
        bfly4<SGN>(r[a], r[a+4], r[a+8], r[a+12]);
        #pragma unroll
        for(int k1=1;k1<4;k1++)
            r[a+4*k1] = cmul(r[a+4*k1], twd<SGN>(stw, 16*a*k1));
    }
    #pragma unroll
    for(int k1=0;k1<4;k1++)
        bfly4<SGN>(r[4*k1], r[4*k1+1], r[4*k1+2], r[4*k1+3]);
    float2 tmp[16];
    #pragma unroll
    for(int i=0;i<16;i++) tmp[((i&3)<<2)|(i>>2)] = r[i];
    #pragma unroll
    for(int i=0;i<16;i++) r[i]=tmp[i];
}

template<int SGN>
__device__ __forceinline__ void fft8(float2 r[8], const float2* stw){
    #pragma unroll
    for(int a=0;a<4;a++){
        float2 u=r[a], v=r[a+4];
        r[a]=cadd(u,v); r[a+4]=csub(u,v);
    }
    #pragma unroll
    for(int a=1;a<4;a++)
        r[a+4]=cmul(r[a+4], twd<SGN>(stw, 32*a));   // W8^a
    bfly4<SGN>(r[0],r[1],r[2],r[3]);
    bfly4<SGN>(r[4],r[5],r[6],r[7]);
    float2 tmp[8];
    #pragma unroll
    for(int m=0;m<8;m++){ int p=m>>2, q=m&3; tmp[2*q+p]=r[m]; }
    #pragma unroll
    for(int m=0;m<8;m++) r[m]=tmp[m];
}

// ---------------- init ----------------
__global__ void k_init_tw(){
    int i = threadIdx.x;
    if (i < 128){
        double a = -2.0*3.14159265358979323846*(double)i/256.0;
        double s, c; sincos(a, &s, &c);
        g_tw[i] = make_float2((float)c, (float)s);
        g_sinT[i] = (float)sin((double)i);
    }
}

// Mc[t][j] = sum_m mtx[t][m] * waveC[j-m+31] (k=63 taps), same for Ms
__global__ void k_build_M(const float* __restrict__ mtx, const float* __restrict__ wave){
    int idx = blockIdx.x*blockDim.x + threadIdx.x;
    if (idx >= 128*128) return;
    int t = idx >> 7, j = idx & 127;
    float ac = 0.f, as = 0.f;
    for (int m = 0; m < 128; m++){
        int tau = j - m + 31;
        if (tau >= 0 && tau < 63){
            float mv = mtx[t*128 + m];
            ac = fmaf(mv, wave[tau],      ac);
            as = fmaf(mv, wave[63 + tau], as);
        }
    }
    g_Mc[idx] = ac; g_Ms[idx] = as;
}

// ---------------- conv+mtx -> packed complex (w-split: 256 blocks) ----------------
__global__ __launch_bounds__(512) void k_conv(const float* __restrict__ feat){
    __shared__ float sx[128*32];
    int bid = blockIdx.x;
    int bd = bid >> 7, r = bid & 127, h = r >> 1, wo = (r & 1)*32;
    const float* src = feat + (size_t)bd*NB + h*64 + wo;
    for (int i = threadIdx.x; i < 128*32; i += 512){
        int t = i >> 5, wl = i & 31;
        sx[i] = src[(size_t)t*4096 + wl];
    }
    __syncthreads();
    float2* dst = g_zc + (size_t)bd*NB + h*64 + wo;
    for (int o = threadIdx.x; o < 128*32; o += 512){
        int t = o >> 5, wl = o & 31;
        float ac = 0.f, as = 0.f;
        const float* mc = g_Mc + t*128;
        const float* ms = g_Ms + t*128;
        #pragma unroll 8
        for (int m = 0; m < 128; m++){
            float xv = sx[m*32 + wl];
            ac = fmaf(mc[m], xv, ac);
            as = fmaf(ms[m], xv, as);
        }
        dst[(size_t)t*4096 + wl] = make_float2(ac, as);
    }
}

// ---------------- forward 2D (H,W) FFT per t-slice (register four-step) ----------------
__global__ __launch_bounds__(512,1) void k_fwd2D(){
    extern __shared__ float2 sm[];           // 128*SMP
    __shared__ float2 stw[128];
    int tid = threadIdx.x;
    if (tid < 128) stw[tid] = g_tw[tid];
    int t = blockIdx.x, bd = blockIdx.y;
    float2* S = sm + 64*SMP;                 // 64 x SMP region
    const float2* src = g_zc + (size_t)bd*NB + (size_t)t*4096;

    for (int i = tid; i < 64*64; i += 512){
        int h = i >> 6, w = i & 63;
        S[h*SMP + w] = src[i];
    }
    __syncthreads();

    // phase W
    {
        int h = tid & 63, r = tid >> 6;
        float2 X[16];
        #pragma unroll
        for (int n2 = 0; n2 < 8; n2++) X[n2] = S[h*SMP + r + 8*n2];
        #pragma unroll
        for (int n2 = 8; n2 < 16; n2++) X[n2] = make_float2(0.f,0.f);
        fft16<1>(X, stw);
        #pragma unroll
        for (int k2 = 1; k2 < 16; k2++) X[k2] = cmul(X[k2], twd<1>(stw, 2*r*k2));
        #pragma unroll
        for (int k2 = 0; k2 < 16; k2++) sm[h*SMP + k2*8 + r] = X[k2];
    }
    __syncthreads();
    {
        int h = tid & 63, rp = tid >> 6;
        #pragma unroll
        for (int kk = 0; kk < 2; kk++){
            int k2 = 2*rp + kk;
            float2 r8[8];
            #pragma unroll
            for (int n1 = 0; n1 < 8; n1++) r8[n1] = sm[h*SMP + k2*8 + n1];
            fft8<1>(r8, stw);
            #pragma unroll
            for (int k1 = 0; k1 < 8; k1++) S[h*SMP + k2 + 16*k1] = r8[k1];
        }
    }

    // phase H: 128 columns in two groups of 64
    for (int g = 0; g < 2; g++){
        __syncthreads();
        int cl = tid & 63, r = tid >> 6;
        float2 X[16];
        #pragma unroll
        for (int n2 = 0; n2 < 8; n2++) X[n2] = S[(r + 8*n2)*SMP + g*64 + cl];
        #pragma unroll
        for (int n2 = 8; n2 < 16; n2++) X[n2] = make_float2(0.f,0.f);
        fft16<1>(X, stw);
        #pragma unroll
        for (int k2 = 1; k2 < 16; k2++) X[k2] = cmul(X[k2], twd<1>(stw, 2*r*k2));
        #pragma unroll
        for (int k2 = 0; k2 < 16; k2++) sm[cl*SMP + k2*8 + r] = X[k2];
        __syncthreads();
        float2* dst = g_bufA + (size_t)bd*VOL + (size_t)t*16384 + g*64 + cl;
        #pragma unroll
        for (int kk = 0; kk < 2; kk++){
            int k2 = 2*r + kk;
            float2 r8[8];
            #pragma unroll
            for (int n1 = 0; n1 < 8; n1++) r8[n1] = sm[cl*SMP + k2*8 + n1];
            fft8<1>(r8, stw);
            #pragma unroll
            for (int k1 = 0; k1 < 8; k1++) dst[(size_t)(k2 + 16*k1)*128] = r8[k1];
        }
    }
}

// ---------------- attention scalar reductions (float4 gathers) ----------------
__device__ double blockReduceD(double v){
    __shared__ double sh[256];
    sh[threadIdx.x] = v; __syncthreads();
    for (int s = 128; s; s >>= 1){ if (threadIdx.x < s) sh[threadIdx.x] += sh[threadIdx.x + s]; __syncthreads(); }
    double r = sh[0]; __syncthreads(); return r;
}
__device__ float blockReduceMin(float v){
    __shared__ float sh[256];
    sh[threadIdx.x] = v; __syncthreads();
    for (int s = 128; s; s >>= 1){ if (threadIdx.x < s) sh[threadIdx.x] = fminf(sh[threadIdx.x], sh[threadIdx.x + s]); __syncthreads(); }
    float r = sh[0]; __syncthreads(); return r;
}
__device__ float blockReduceMax(float v){
    __shared__ float sh[256];
    sh[threadIdx.x] = v; __syncthreads();
    for (int s = 128; s; s >>= 1){ if (threadIdx.x < s) sh[threadIdx.x] = fmaxf(sh[threadIdx.x], sh[threadIdx.x + s]); __syncthreads(); }
    float r = sh[0]; __syncthreads(); return r;
}

// j4 in [0, NB/4); all wraps are 4-aligned so float4 loads stay contiguous+aligned.
__device__ __forceinline__ float4 loadL4(const float* K, int j, float& pe){
    int tl = j >> 12, hl = (j >> 6) & 63, wl = j & 63;
    pe = g_sinT[tl];
    return *(const float4*)&K[((192 + tl) & 255)*16384 + ((96 + hl) & 127)*128 + ((96 + wl) & 127)];
}
__device__ __forceinline__ float4 loadH4(const float* K, int j, float& pe){
    int tl = j >> 12, hl = (j >> 6) & 63, wl = j & 63;
    pe = g_sinT[tl];
    return *(const float4*)&K[(64 + tl)*16384 + (32 + hl)*128 + (32 + wl)];
}

__global__ __launch_bounds__(256) void k_redA(const float* __restrict__ invr, const float* __restrict__ invi){
    int f = blockIdx.y;
    const float* K = f ? invi : invr;
    int j = (blockIdx.x*256 + threadIdx.x)*4;     // RBLK*256*4 == NB exactly
    float pe;
    float4 vL = loadL4(K, j, pe);
    float4 vH = loadH4(K, j, pe);
    double sum = (double)vL.x + (double)vL.y + (double)vL.z + (double)vL.w;
    float mnL = fminf(fminf(vL.x, vL.y), fminf(vL.z, vL.w)) + pe;
    float mxL = fmaxf(fmaxf(vL.x, vL.y), fmaxf(vL.z, vL.w)) + pe;
    float mnH = fminf(fminf(vH.x, vH.y), fminf(vH.z, vH.w)) + pe;
    float mxH = fmaxf(fmaxf(vH.x, vH.y), fmaxf(vH.z, vH.w)) + pe;
    sum = blockReduceD(sum);
    mnL = blockReduceMin(mnL); mxL = blockReduceMax(mxL);
    mnH = blockReduceMin(mnH); mxH = blockReduceMax(mxH);
    if (threadIdx.x == 0){
        g_pD[f][blockIdx.x] = sum;
        g_pMnL[f][blockIdx.x] = mnL; g_pMxL[f][blockIdx.x] = mxL;
        g_pMnH[f][blockIdx.x] = mnH; g_pMxH[f][blockIdx.x] = mxH;
    }
}

__global__ void k_combA(const float* __restrict__ wp, const float* __restrict__ bp){
    int f = blockIdx.x, i = threadIdx.x;
    __shared__ double sd[256]; __shared__ float s1[256], s2[256], s3[256], s4[256];
    sd[i] = g_pD[f][i] + g_pD[f][i+256];
    s1[i] = fminf(g_pMnL[f][i], g_pMnL[f][i+256]);
    s2[i] = fmaxf(g_pMxL[f][i], g_pMxL[f][i+256]);
    s3[i] = fminf(g_pMnH[f][i], g_pMnH[f][i+256]);
    s4[i] = fmaxf(g_pMxH[f][i], g_pMxH[f][i+256]);
    __syncthreads();
    for (int s = 128; s; s >>= 1){
        if (i < s){
            sd[i] += sd[i+s];
            s1[i] = fminf(s1[i], s1[i+s]); s2[i] = fmaxf(s2[i], s2[i+s]);
            s3[i] = fminf(s3[i], s3[i+s]); s4[i] = fmaxf(s4[i], s4[i+s]);
        }
        __syncthreads();
    }
    if (i == 0){
        float W = *wp, B = *bp;
        float scal1 = W*(float)(sd[0]/(double)NB) + B;
        float a1 = scal1*W, c1 = scal1*B;
        g_a1[f] = a1; g_c1[f] = c1;
        g_M1f[f] = (a1 >= 0.f ? a1*s2[0] : a1*s1[0]) + c1;
        g_mnH[f] = s3[0]; g_mxH[f] = s4[0];
    }
}

__global__ __launch_bounds__(256) void k_redB(const float* __restrict__ invr, const float* __restrict__ invi){
    int f = blockIdx.y; const float* K = f ? invi : invr;
    float a1 = g_a1[f], c1 = g_c1[f], M1 = g_M1f[f];
    int j = (blockIdx.x*256 + threadIdx.x)*4;
    float pe;
    float4 vL = loadL4(K, j, pe);
    float b = c1 - M1 + a1*pe;
    double acc = (double)__expf(fmaf(a1, vL.x, b)) + (double)__expf(fmaf(a1, vL.y, b))
               + (double)__expf(fmaf(a1, vL.z, b)) + (double)__expf(fmaf(a1, vL.w, b));
    acc = blockReduceD(acc);
    if (threadIdx.x == 0) g_pD[f][blockIdx.x] = acc;
}
__global__ void k_combB(){
    int f = blockIdx.x, i = threadIdx.x;
    __shared__ double sd[256];
    sd[i] = g_pD[f][i] + g_pD[f][i+256]; __syncthreads();
    for (int s = 128; s; s >>= 1){ if (i < s) sd[i] += sd[i+s]; __syncthreads(); }
    if (i == 0) g_Z1i[f] = (float)(1.0/sd[0]);
}

__global__ __launch_bounds__(256) void k_redC(const float* __restrict__ invr, const float* __restrict__ invi){
    int f = blockIdx.y; const float* K = f ? invi : invr;
    float a1 = g_a1[f], c1 = g_c1[f], M1 = g_M1f[f], Z1i = g_Z1i[f];
    int j = (blockIdx.x*256 + threadIdx.x)*4;
    float pe;
    float4 vL = loadL4(K, j, pe);
    float kL[4] = {vL.x+pe, vL.y+pe, vL.z+pe, vL.w+pe};
    double acc = 0.0;
    #pragma unroll
    for (int q = 0; q < 4; q++){
        float sm = __expf(fmaf(a1, kL[q], c1) - M1) * Z1i;
        acc += (double)(kL[q] / (1.f + __expf(-sm)));
    }
    acc = blockReduceD(acc);
    if (threadIdx.x == 0) g_pD[f][blockIdx.x] = acc;
}
__global__ void k_combC(const float* __restrict__ wp, const float* __restrict__ bp){
    int f = blockIdx.x, i = threadIdx.x;
    __shared__ double sd[256];
    sd[i] = g_pD[f][i] + g_pD[f][i+256]; __syncthreads();
    for (int s = 128; s; s >>= 1){ if (i < s) sd[i] += sd[i+s]; __syncthreads(); }
    if (i == 0){
        float W = *wp, B = *bp;
        float scal2 = W*(float)(sd[0]/(double)NB) + B;
        float a2 = scal2*W, c2 = scal2*B;
        g_a2[f] = a2; g_c2[f] = c2;
        g_M2f[f] = (a2 >= 0.f ? a2*g_mxH[f] : a2*g_mnH[f]) + c2;
    }
}

__global__ __launch_bounds__(256) void k_redD(const float* __restrict__ invr, const float* __restrict__ invi){
    int f = blockIdx.y; const float* K = f ? invi : invr;
    float a2 = g_a2[f], c2 = g_c2[f], M2 = g_M2f[f];
    int j = (blockIdx.x*256 + threadIdx.x)*4;
    float pe;
    float4 vH = loadH4(K, j, pe);
    float b = c2 - M2 + a2*pe;
    double acc = (double)__expf(fmaf(a2, vH.x, b)) + (double)__expf(fmaf(a2, vH.y, b))
               + (double)__expf(fmaf(a2, vH.z, b)) + (double)__expf(fmaf(a2, vH.w, b));
    acc = blockReduceD(acc);
    if (threadIdx.x == 0) g_pD[f][blockIdx.x] = acc;
}
__global__ void k_combD(){
    int f = blockIdx.x, i = threadIdx.x;
    __shared__ double sd[256];
    sd[i] = g_pD[f][i] + g_pD[f][i+256]; __syncthreads();
    for (int s = 128; s; s >>= 1){ if (i < s) sd[i] += sd[i+s]; __syncthreads(); }
    if (i == 0) g_Z2i[f] = (float)(1.0/sd[0]);
}

// ---------------- filtered W: pass-through region (no scalars needed) ----------------
__global__ __launch_bounds__(256) void k_filterW_pass(const float* __restrict__ invr, const float* __restrict__ invi){
    int idx = blockIdx.x*256 + threadIdx.x;
    int t = idx >> 14, h = (idx >> 7) & 127, w = idx & 127;
    bool inH = ((unsigned)(t-64) < 128u) && ((unsigned)(h-32) < 64u) && ((unsigned)(w-32) < 64u);
    bool inL = (((t+64)&255) < 128) && (((h+32)&127) < 64) && (((w+32)&127) < 64);
    if (!(inH || inL)){
        const float sc = 1.f/256.f;
        g_Wf[idx] = make_float2(invr[idx]*sc, invi[idx]*sc);
    }
}

// ---------------- filtered W: the two attention block regions (after combD) -----------
__global__ __launch_bounds__(256) void k_filterW_blocks(const float* __restrict__ invr, const float* __restrict__ invi){
    int b = blockIdx.x*256 + threadIdx.x;      // 0 .. 2*NB
    int region = b >> 19;                       // NB = 2^19
    int j = b & (NB - 1);
    int tl = j >> 12, hl = (j >> 6) & 63, wl = j & 63;
    int t, h, w;
    float a0, c0, M0, Zi0, a1f, c1f, M1f_, Zi1;
    if (region == 0){   // high block -> second-stage scalars
        t = tl + 64; h = hl + 32; w = wl + 32;
        a0 = g_a2[0]; c0 = g_c2[0]; M0 = g_M2f[0]; Zi0 = g_Z2i[0];
        a1f = g_a2[1]; c1f = g_c2[1]; M1f_ = g_M2f[1]; Zi1 = g_Z2i[1];
    } else {            // low (wrapped corner) block -> first-stage scalars
        t = (192 + tl) & 255; h = (96 + hl) & 127; w = (96 + wl) & 127;
        a0 = g_a1[0]; c0 = g_c1[0]; M0 = g_M1f[0]; Zi0 = g_Z1i[0];
        a1f = g_a1[1]; c1f = g_c1[1]; M1f_ = g_M1f[1]; Zi1 = g_Z1i[1];
    }
    size_t idx = (size_t)t*16384 + (size_t)h*128 + w;
    float pe = g_sinT[tl];
    float v0 = invr[idx] + pe, v1 = invi[idx] + pe;
    float sm0 = __expf(fmaf(a0, v0, c0) - M0) * Zi0;
    float sm1 = __expf(fmaf(a1f, v1, c1f) - M1f_) * Zi1;
    const float sc = 1.f/256.f;
    float w0 = v0 / (1.f + __expf(-sm0)) * sc;
    float w1 = v1 / (1.f + __expf(-sm1)) * sc;
    g_Wf[idx] = make_float2(w0, w1);
}

// ---------------- fused T (16x16 four-step, register FFTs) ----------------
__global__ __launch_bounds__(256,2) void k_fusedT(){
    extern __shared__ unsigned char smraw[];
    float2* bufA = (float2*)smraw;           // 16 lanes x 257
    float2* bufB = bufA + 16*257;
    __shared__ float2 stw[128];
    int tid = threadIdx.x, lane = tid & 15, role = tid >> 4;
    if (tid < 128) stw[tid] = g_tw[tid];
    int wb = blockIdx.x << 4, h = blockIdx.y, bd = blockIdx.z;
    int w = wb + lane;

    float2 X[16];
    const float2* ZS = g_bufA + (size_t)bd*VOL + (size_t)h*128 + w;
    #pragma unroll
    for (int j = 0; j < 8; j++) X[j] = ZS[(size_t)(role + 16*j)*16384];
    #pragma unroll
    for (int j = 8; j < 16; j++) X[j] = make_float2(0.f, 0.f);
    __syncthreads();

    fft16<1>(X, stw);
    int base = lane*257;
    #pragma unroll
    for (int j = 1; j < 16; j++) X[j] = cmul(X[j], twd<1>(stw, role*j));
    #pragma unroll
    for (int j = 0; j < 16; j++) bufA[base + j*16 + role] = X[j];
    __syncthreads();
    float2 S[16];
    #pragma unroll
    for (int n1 = 0; n1 < 16; n1++) S[n1] = bufA[base + role*16 + n1];
    fft16<1>(S, stw);

    const float2* WD = g_Wf + (size_t)h*128 + w;
    float2 A[16];
    #pragma unroll
    for (int j = 0; j < 16; j++){
        float2 wd = WD[(size_t)(role + 16*j)*16384];
        A[j] = cmul(wd, S[j]);
    }
    fft16<-1>(A, stw);
    __syncthreads();
    #pragma unroll
    for (int t1 = 0; t1 < 16; t1++)
        bufA[base + t1*16 + role] = cmul(A[t1], twd<-1>(stw, role*t1));

    int hn = (128 - h) & 127, wn = (128 - w) & 127;
    const float2* WR = g_Wf + (size_t)hn*128 + wn;
    #pragma unroll
    for (int j = 0; j < 16; j++){
        int kn = (256 - (role + 16*j)) & 255;
        float2 wr = WR[(size_t)kn*16384];
        A[j] = cmul(make_float2(wr.x, -wr.y), S[j]);
    }
    fft16<-1>(A, stw);
    #pragma unroll
    for (int t1 = 0; t1 < 16; t1++)
        bufB[base + t1*16 + role] = cmul(A[t1], twd<-1>(stw, role*t1));
    __syncthreads();

    float2* dP = g_bufB + (size_t)(2*bd)*VOL + (size_t)h*128 + w;
    #pragma unroll
    for (int K = 0; K < 16; K++) A[K] = bufA[base + role*16 + K];
    fft16<-1>(A, stw);
    #pragma unroll
    for (int t2 = 0; t2 < 8; t2++) dP[(size_t)(role + 16*t2)*16384] = A[t2];
    #pragma unroll
    for (int K = 0; K < 16; K++) A[K] = bufB[base + role*16 + K];
    fft16<-1>(A, stw);
    #pragma unroll
    for (int t2 = 0; t2 < 8; t2++) dP[(size_t)VOL + (size_t)(role + 16*t2)*16384] = A[t2];
}

// ---------------- inverse 2D (H,W) per t-slice (register four-step) -----------------
__global__ __launch_bounds__(512,1) void k_inv2D(){
    extern __shared__ float2 sm[];           // 128*SMP: rows 0..63 = exchange E, 64..127 = O
    __shared__ float2 stw[128];
    __shared__ float2 qd[64*65];
    int tid = threadIdx.x;
    if (tid < 128){ stw[tid] = g_tw[tid]; }
    int t = blockIdx.x, bd = blockIdx.y;
    float2* O = sm + 64*SMP;

    for (int pass = 0; pass < 2; pass++){
        const float2* src = g_bufB + (size_t)(2*bd + pass)*VOL + (size_t)t*16384;
        for (int g = 0; g < 2; g++){
            __syncthreads();
            int cl = tid & 63, r = tid >> 6;
            float2 X[16];
            #pragma unroll
            for (int n2 = 0; n2 < 16; n2++) X[n2] = src[(size_t)(r + 8*n2)*128 + g*64 + cl];
            fft16<-1>(X, stw);
            #pragma unroll
            for (int k2 = 1; k2 < 16; k2++) X[k2] = cmul(X[k2], twd<-1>(stw, 2*r*k2));
            #pragma unroll
            for (int k2 = 0; k2 < 16; k2++) sm[cl*SMP + k2*8 + r] = X[k2];
            __syncthreads();
            #pragma unroll
            for (int kk = 0; kk < 2; kk++){
                int k2 = 2*r + kk;
                float2 r8[8];
                #pragma unroll
                for (int n1 = 0; n1 < 8; n1++) r8[n1] = sm[cl*SMP + k2*8 + n1];
                fft8<-1>(r8, stw);
                #pragma unroll
                for (int k1 = 0; k1 < 4; k1++) O[(k2 + 16*k1)*SMP + g*64 + cl] = r8[k1];
            }
        }
        __syncthreads();
        {
            int h = tid & 63, r = tid >> 6;
            float2 X[16];
            #pragma unroll
            for (int n2 = 0; n2 < 16; n2++) X[n2] = O[h*SMP + r + 8*n2];
            fft16<-1>(X, stw);
            #pragma unroll
            for (int k2 = 1; k2 < 16; k2++) X[k2] = cmul(X[k2], twd<-1>(stw, 2*r*k2));
            #pragma unroll
            for (int k2 = 0; k2 < 16; k2++) sm[h*SMP + k2*8 + r] = X[k2];
        }
        __syncthreads();
        {
            int h = tid & 63, r = tid >> 6;
            float* fq = (float*)O;
            #pragma unroll
            for (int kk = 0; kk < 2; kk++){
                int k2 = 2*r + kk;
                float2 r8[8];
                #pragma unroll
                for (int n1 = 0; n1 < 8; n1++) r8[n1] = sm[h*SMP + k2*8 + n1];
                fft8<-1>(r8, stw);
                if (pass == 0){
                    #pragma unroll
                    for (int k1 = 0; k1 < 4; k1++)
                        qd[h*65 + k2 + 16*k1] = r8[k1];
                } else {
                    const float S2 = 1.f/268435456.f;   // (1/16384)^2
                    #pragma unroll
                    for (int k1 = 0; k1 < 4; k1++){
                        int w = k2 + 16*k1;
                        float2 P = qd[h*65 + w];
                        float2 R = r8[k1];
                        float Sr = (P.x*R.x + P.y*R.y)*S2;
                        float Si = (P.y*R.x - P.x*R.y)*S2;
                        float mag = fmaxf(0.5f*(sqrtf(Sr*Sr + Si*Si) + Sr), 0.f);
                        fq[h*65 + w] = sqrtf(mag);
                    }
                }
            }
        }
        if (pass == 1){
            __syncthreads();
            const float* fq = (const float*)O;
            float* dst = g_sq + (size_t)bd*NB + (size_t)t*4096;
            for (int i = tid; i < 4096; i += 512)
                dst[i] = fq[(i >> 6)*65 + (i & 63)];
        }
    }
}

// ---------------- final mtxi matmul along T (w-split: 256 blocks) ----------------
__global__ __launch_bounds__(512) void k_final(const float* __restrict__ mtxi, float* __restrict__ out){
    __shared__ float sx[128*32];
    int bid = blockIdx.x;
    int bd = bid >> 7, r = bid & 127, h = r >> 1, wo = (r & 1)*32;
    const float* src = g_sq + (size_t)bd*NB + h*64 + wo;
    for (int i = threadIdx.x; i < 128*32; i += 512){
        int t = i >> 5, wl = i & 31;
        sx[i] = src[(size_t)t*4096 + wl];
    }
    __syncthreads();
    float* dst = out + (size_t)bd*NB + h*64 + wo;
    for (int o = threadIdx.x; o < 128*32; o += 512){
        int t = o >> 5, wl = o & 31;
        float acc = 0.f;
        const float* mi = mtxi + t*128;
        #pragma unroll 8
        for (int m = 0; m < 128; m++) acc = fmaf(mi[m], sx[m*32 + wl], acc);
        dst[(size_t)t*4096 + wl] = acc;
    }
}

// ---------------- launch ----------------
#define TILE_SMEM (128*SMP*8)
#define FT_SMEM   (2*16*257*8)

extern "C" void kernel_launch(void* const* d_in, const int* in_sizes, int n_in,
                              void* d_out, int out_size){
    const float *feature = 0, *conv_w = 0, *conv_b = 0, *wave = 0;
    const float *invr = 0, *invi = 0, *mtx = 0, *mtxi = 0;
    int scal_seen = 0, mat_seen = 0, psf_seen = 0;
    for (int i = 0; i < n_in; i++){
        const float* p = (const float*)d_in[i];
        int s = in_sizes[i];
        if      (s == 1)       { if (scal_seen++ == 0) conv_w = p; else conv_b = p; }
        else if (s == 126)     wave = p;
        else if (s == 16384)   { if (mat_seen++ == 0) mtx = p; else mtxi = p; }
        else if (s == 4194304) { if (psf_seen++ == 0) invr = p; else invi = p; }
        else if (s == 1048576) feature = p;
    }
    float* out = (float*)d_out;

    // lazy one-time resources (no device memory; same launches every call)
    static cudaStream_t s2 = 0;
    static cudaEvent_t  evFork = 0, evJoin = 0;
    static int attrs_set = 0;
    if (!s2){
        cudaStreamCreateWithFlags(&s2, cudaStreamNonBlocking);
        cudaEventCreateWithFlags(&evFork, cudaEventDisableTiming);
        cudaEventCreateWithFlags(&evJoin, cudaEventDisableTiming);
    }
    if (!attrs_set){
        cudaFuncSetAttribute(k_fwd2D,  cudaFuncAttributeMaxDynamicSharedMemorySize, TILE_SMEM);
        cudaFuncSetAttribute(k_inv2D,  cudaFuncAttributeMaxDynamicSharedMemorySize, TILE_SMEM);
        cudaFuncSetAttribute(k_fusedT, cudaFuncAttributeMaxDynamicSharedMemorySize, FT_SMEM);
        attrs_set = 1;
    }

    k_init_tw<<<1,128>>>();

    // fork: side stream runs the attention-scalar chain + block-region filter
    cudaEventRecord(evFork, 0);
    cudaStreamWaitEvent(s2, evFork, 0);

    k_redA<<<dim3(RBLK,2),256,0,s2>>>(invr, invi);
    k_combA<<<2,256,0,s2>>>(conv_w, conv_b);
    k_redB<<<dim3(RBLK,2),256,0,s2>>>(invr, invi);
    k_combB<<<2,256,0,s2>>>();
    k_redC<<<dim3(RBLK,2),256,0,s2>>>(invr, invi);
    k_combC<<<2,256,0,s2>>>(conv_w, conv_b);
    k_redD<<<dim3(RBLK,2),256,0,s2>>>(invr, invi);
    k_combD<<<2,256,0,s2>>>();
    k_filterW_blocks<<<2*NB/256,256,0,s2>>>(invr, invi);
    cudaEventRecord(evJoin, s2);

    // main stream: forward path + pass-through filter region (disjoint writes)
    k_build_M<<<64,256>>>(mtx, wave);
    k_conv<<<256,512>>>(feature);
    k_fwd2D<<<dim3(128,2),512,TILE_SMEM>>>();
    k_filterW_pass<<<VOL/256,256>>>(invr, invi);

    // join before fusedT (needs g_bufA AND all of g_Wf)
    cudaStreamWaitEvent(0, evJoin, 0);

    k_fusedT<<<dim3(8,128,2),256,FT_SMEM>>>();
    k_inv2D<<<dim3(128,2),512,TILE_SMEM>>>();
    k_final<<<256,512>>>(mtxi, out);
}